// round 4
// baseline (speedup 1.0000x reference)
#include <cuda_runtime.h>
#include <cuda_bf16.h>

// Problem constants (fixed by the dataset)
#define BB 16
#define TT 512
#define DD 384
#define D4 (DD / 4)          // 96 float4 per row
#define MAXLEN 4096
#define FPB 16               // frames per block
#define CPB (MAXLEN / FPB)   // 256 chunks (blocks) per batch
#define NTHR 512

// ---------------------------------------------------------------------------
// Fused kernel built ONLY from R2-proven components:
//  - Hillis-Steele inclusive scan in shared memory (identical to passing R2)
//  - scatter inversion: token t owns frames [cum[t-1], min(cum[t], lim))
//    (identical semantics to passing R2, windowed to this block's 16 frames)
//  - coalesced float4 gather + streaming stores
// blockIdx.x = b * CPB + chunk; block covers frames [chunk*FPB, chunk*FPB+FPB)
// ---------------------------------------------------------------------------
__global__ void __launch_bounds__(NTHR)
lr_fused(const float4* __restrict__ x, const int* __restrict__ dur,
         float* __restrict__ out, int mode) {
    __shared__ int s[TT];        // inclusive cumsum (Hillis-Steele)
    __shared__ int fidx[FPB];    // frame -> token index for this window, -1 = zero

    const int b     = blockIdx.x >> 8;        // / CPB (CPB == 256)
    const int chunk = blockIdx.x & (CPB - 1);
    const int t     = threadIdx.x;

    // ---- inclusive scan of durations (exact R2 code) ----
    const int v = __ldg(&dur[b * TT + t]);
    s[t] = v;
    __syncthreads();
    #pragma unroll
    for (int off = 1; off < TT; off <<= 1) {
        int add = (t >= off) ? s[t - off] : 0;
        __syncthreads();
        s[t] += add;
        __syncthreads();
    }

    const int end   = s[t];
    const int start = end - v;
    const int mel   = s[TT - 1];
    const int lim   = mel < MAXLEN ? mel : MAXLEN;
    const int f0    = chunk * FPB;

    // ---- scatter inversion into this block's window (R2 semantics) ----
    if (t < FPB) fidx[t] = -1;
    __syncthreads();

    {
        const int e2 = end < lim ? end : lim;                // clip to valid
        int a  = start > f0 ? start : f0;                    // window intersect
        int bd = e2 < (f0 + FPB) ? e2 : (f0 + FPB);
        for (int f = a; f < bd; ++f) fidx[f - f0] = t;       // durations < 8
    }

    // mel_len tail (output 1), written once per batch by chunk 0
    if (chunk == 0 && t == 0 && mode) {
        const long long base = (long long)BB * MAXLEN * DD;
        if (mode == 1)      out[base + b] = (float)mel;
        else                ((long long*)(out + base))[b] = (long long)mel;
    }
    __syncthreads();

    // ---- gather + streaming store: FPB*96 = 1536 float4, 3 per thread ----
    const float4* xb = x + (size_t)b * TT * D4;
    float4* ob = (float4*)out + ((size_t)b * MAXLEN + f0) * D4;
    #pragma unroll
    for (int k = 0; k < (FPB * D4) / NTHR; ++k) {
        const int g  = t + k * NTHR;      // 0..1535, contiguous stores
        const int fl = g / D4;
        const int d4 = g - fl * D4;
        const int id = fidx[fl];
        float4 val = make_float4(0.f, 0.f, 0.f, 0.f);
        if (id >= 0) val = __ldg(&xb[id * D4 + d4]);
        __stcs(&ob[g], val);
    }
}

extern "C" void kernel_launch(void* const* d_in, const int* in_sizes, int n_in,
                              void* d_out, int out_size) {
    const float* x   = (const float*)d_in[0];
    const int*   dur = (const int*)d_in[1];   // int32 (JAX x64 disabled)

    const long long base = (long long)BB * MAXLEN * DD;   // 25,165,824 f32
    int mode = 0;
    if ((long long)out_size == base + BB)            mode = 1;  // mel as f32
    else if ((long long)out_size == base + 2 * BB)   mode = 2;  // mel as i64

    lr_fused<<<BB * CPB, NTHR>>>((const float4*)x, dur, (float*)d_out, mode);
}

// round 5
// speedup vs baseline: 1.3051x; 1.3051x over previous
#include <cuda_runtime.h>
#include <cuda_bf16.h>

// Problem constants (fixed by the dataset)
#define BB 16
#define TT 512
#define DD 384
#define D4 (DD / 4)          // 96 float4 per row
#define MAXLEN 4096
#define FPB 32               // frames per block
#define CPB (MAXLEN / FPB)   // 128 chunks (blocks) per batch
#define NTHR 512
#define NWARP (NTHR / 32)    // 16

// ---------------------------------------------------------------------------
// Fused kernel:
//  - warp-shuffle inclusive scan of durations (2 barriers, no smem scan traffic)
//  - scatter inversion (proven R4): token t owns frames [cum[t-1], min(cum[t],lim))
//  - coalesced float4 gather + streaming stores
// blockIdx.x = b * CPB + chunk; block covers frames [chunk*FPB, chunk*FPB+FPB)
// ---------------------------------------------------------------------------
__global__ void __launch_bounds__(NTHR)
lr_fused(const float4* __restrict__ x, const int* __restrict__ dur,
         float* __restrict__ out, int mode) {
    __shared__ int wsum[NWARP];
    __shared__ int fidx[FPB];    // frame -> token index for this window, -1 = zero
    __shared__ int s_mel;

    const int b     = blockIdx.x / CPB;
    const int chunk = blockIdx.x - b * CPB;
    const int t     = threadIdx.x;
    const int lane  = t & 31;
    const int w     = t >> 5;

    // ---- inclusive scan of durations: warp shuffle + warp-total fixup ----
    const int v = __ldg(&dur[b * TT + t]);
    int sc = v;
    #pragma unroll
    for (int o = 1; o < 32; o <<= 1) {
        int n = __shfl_up_sync(0xffffffffu, sc, o);
        if (lane >= o) sc += n;
    }
    if (lane == 31) wsum[w] = sc;
    if (t < FPB) fidx[t] = -1;
    __syncthreads();
    if (w == 0 && lane < NWARP) {
        int ws = wsum[lane];
        #pragma unroll
        for (int o = 1; o < NWARP; o <<= 1) {
            int n = __shfl_up_sync(0x0000ffffu, ws, o);
            if (lane >= o) ws += n;
        }
        wsum[lane] = ws;
        if (lane == NWARP - 1) s_mel = ws;   // total = mel_len
    }
    __syncthreads();

    const int end   = sc + (w ? wsum[w - 1] : 0);   // inclusive cum[t]
    const int start = end - v;                       // cum[t-1]
    const int mel   = s_mel;
    const int lim   = mel < MAXLEN ? mel : MAXLEN;
    const int f0    = chunk * FPB;

    // ---- scatter inversion into this block's window (proven R4 semantics) ----
    {
        const int e2 = end < lim ? end : lim;                 // clip to valid
        int a  = start > f0 ? start : f0;                     // window intersect
        int bd = e2 < (f0 + FPB) ? e2 : (f0 + FPB);
        for (int f = a; f < bd; ++f) fidx[f - f0] = t;        // durations < 8
    }

    // mel_len tail (output 1), written once per batch by chunk 0
    if (chunk == 0 && t == 0 && mode) {
        const long long base = (long long)BB * MAXLEN * DD;
        if (mode == 1)      out[base + b] = (float)mel;
        else                ((long long*)(out + base))[b] = (long long)mel;
    }
    __syncthreads();

    // ---- gather + streaming store: FPB*96 = 3072 float4, 6 per thread ----
    const float4* xb = x + (size_t)b * TT * D4;
    float4* ob = (float4*)out + ((size_t)b * MAXLEN + f0) * D4;
    #pragma unroll
    for (int k = 0; k < (FPB * D4) / NTHR; ++k) {
        const int g  = t + k * NTHR;      // contiguous, fully coalesced
        const int fl = g / D4;
        const int d4 = g - fl * D4;
        const int id = fidx[fl];
        float4 val = make_float4(0.f, 0.f, 0.f, 0.f);
        if (id >= 0) val = __ldg(&xb[id * D4 + d4]);
        __stcs(&ob[g], val);
    }
}

extern "C" void kernel_launch(void* const* d_in, const int* in_sizes, int n_in,
                              void* d_out, int out_size) {
    const float* x   = (const float*)d_in[0];
    const int*   dur = (const int*)d_in[1];   // int32 (JAX x64 disabled)

    const long long base = (long long)BB * MAXLEN * DD;   // 25,165,824 f32
    int mode = 0;
    if ((long long)out_size == base + BB)            mode = 1;  // mel as f32
    else if ((long long)out_size == base + 2 * BB)   mode = 2;  // mel as i64

    lr_fused<<<BB * CPB, NTHR>>>((const float4*)x, dur, (float*)d_out, mode);
}